// round 1
// baseline (speedup 1.0000x reference)
#include <cuda_runtime.h>
#include <cstdint>
#include <math.h>

// Problem constants
#define H_HEADS 16
#define BATCH   2
#define L       1024
#define D       64
#define USAMP   7097
#define USEL    34
#define DMODEL  (H_HEADS * D)   // 1024

// ---------------- scratch (static device globals; no allocation) ----------------
__device__ float g_S[BATCH][L][L];            // q @ k^T per batch (8 MB)
__device__ int   g_cnt[H_HEADS][BATCH][L];    // sample histograms
__device__ float g_M[BATCH][H_HEADS][L];      // sparsity measure
__device__ int   g_top[BATCH][H_HEADS][USEL]; // selected query indices
__device__ float g_meanv[BATCH][D];           // mean over keys of v
__device__ float g_attn[BATCH][L][DMODEL];    // concatenated head outputs (8 MB)

// ---------------- threefry2x32 (JAX-compatible) ----------------
__device__ __forceinline__ uint32_t rotl32(uint32_t x, int d) {
    return (x << d) | (x >> (32 - d));
}

__device__ __forceinline__ void threefry2x32(uint32_t k0, uint32_t k1,
                                             uint32_t x0, uint32_t x1,
                                             uint32_t& o0, uint32_t& o1) {
    uint32_t ks2 = k0 ^ k1 ^ 0x1BD11BDAu;
    x0 += k0; x1 += k1;
#define TFR(r) { x0 += x1; x1 = rotl32(x1, (r)); x1 ^= x0; }
    TFR(13) TFR(15) TFR(26) TFR(6)   x0 += k1;  x1 += ks2 + 1u;
    TFR(17) TFR(29) TFR(16) TFR(24)  x0 += ks2; x1 += k0 + 2u;
    TFR(13) TFR(15) TFR(26) TFR(6)   x0 += k0;  x1 += k1 + 3u;
    TFR(17) TFR(29) TFR(16) TFR(24)  x0 += k1;  x1 += ks2 + 4u;
    TFR(13) TFR(15) TFR(26) TFR(6)   x0 += ks2; x1 += k0 + 5u;
#undef TFR
    o0 = x0; o1 = x1;
}

// ---------------- kernel 0: zero the histograms ----------------
__global__ void k_zero_cnt() {
    int i = blockIdx.x * blockDim.x + threadIdx.x;
    if (i < H_HEADS * BATCH * L) ((int*)g_cnt)[i] = 0;
}

// ---------------- kernel 1: sampled-index histograms via threefry ----------------
// Replicates (partitionable threefry):
//   root = (0,42); head_key[h] = tf(root, (0,h))            [split fold-like]
//   k2   = tf(head_key, (0,1))                               [randint's 2nd subkey]
//   bits(i) = b1 ^ b2 of tf(k2, (0,i)),  idx = bits % 1024   [multiplier==0 path]
__global__ void k_idx_counts() {
    int i = blockIdx.x * blockDim.x + threadIdx.x;  // flat sample index, (B,USAMP) row-major
    int h = blockIdx.y;
    if (i >= BATCH * USAMP) return;
    uint32_t hk0, hk1, s0, s1, b1, b2;
    threefry2x32(0u, 42u, 0u, (uint32_t)h, hk0, hk1);
    threefry2x32(hk0, hk1, 0u, 1u, s0, s1);
    threefry2x32(s0, s1, 0u, (uint32_t)i, b1, b2);
    uint32_t bits = b1 ^ b2;
    int j = (int)(bits & 1023u);
    int b = i / USAMP;
    atomicAdd(&g_cnt[h][b][j], 1);
}

// ---------------- kernel 2: S[b] = q[b] @ k[b]^T  (1024x1024, depth 64) ----------------
__global__ void k_scores(const float* __restrict__ q, const float* __restrict__ k) {
    __shared__ float qs[64][65];
    __shared__ float ks[64][65];
    int b  = blockIdx.z;
    int i0 = blockIdx.y * 64, j0 = blockIdx.x * 64;
    int tid = threadIdx.x;
    for (int t = tid; t < 4096; t += 256) {
        int r = t >> 6, c = t & 63;
        qs[r][c] = q[((size_t)b * L + i0 + r) * D + c];
        ks[r][c] = k[((size_t)b * L + j0 + r) * D + c];
    }
    __syncthreads();
    int tx = tid & 15, ty = tid >> 4;
    float acc[4][4] = {};
#pragma unroll 8
    for (int d = 0; d < 64; d++) {
        float a[4], bb[4];
#pragma unroll
        for (int r = 0; r < 4; r++) a[r] = qs[ty * 4 + r][d];
#pragma unroll
        for (int c = 0; c < 4; c++) bb[c] = ks[tx * 4 + c][d];
#pragma unroll
        for (int r = 0; r < 4; r++)
#pragma unroll
            for (int c = 0; c < 4; c++)
                acc[r][c] += a[r] * bb[c];
    }
#pragma unroll
    for (int r = 0; r < 4; r++)
#pragma unroll
        for (int c = 0; c < 4; c++)
            g_S[b][i0 + ty * 4 + r][j0 + tx * 4 + c] = acc[r][c];
}

// ---------------- kernel 3: M = masked max - count-weighted mean ----------------
__global__ void k_measure() {
    int b = blockIdx.z, h = blockIdx.y;
    int q0 = blockIdx.x * 8;
    __shared__ int cnt_s[L];
    int tid = threadIdx.x;
    for (int j = tid; j < L; j += 256) cnt_s[j] = g_cnt[h][b][j];
    __syncthreads();
    int w = tid >> 5, lane = tid & 31;
    int qr = q0 + w;
    const float* Srow = g_S[b][qr];
    float mx = -3.4e38f;
    float sum = 0.f;
    for (int j = lane; j < L; j += 32) {
        float s = Srow[j];
        int   c = cnt_s[j];
        if (c) mx = fmaxf(mx, s);
        sum += (float)c * s;
    }
#pragma unroll
    for (int off = 16; off; off >>= 1) {
        mx  = fmaxf(mx, __shfl_down_sync(0xffffffffu, mx, off));
        sum += __shfl_down_sync(0xffffffffu, sum, off);
    }
    if (lane == 0) g_M[b][h][qr] = mx - sum / 7097.0f;
}

// ---------------- kernel 4: iterative top-34 (set semantics; tie -> lower index) ----------------
__global__ void k_topk() {
    int h = blockIdx.x, b = blockIdx.y;
    __shared__ float m[L];
    __shared__ float bv[256];
    __shared__ int   bi[256];
    int tid = threadIdx.x;
    for (int j = tid; j < L; j += 256) m[j] = g_M[b][h][j];
    __syncthreads();
    for (int t = 0; t < USEL; t++) {
        float best = -3.4e38f; int bidx = L;
        for (int j = tid; j < L; j += 256) {
            float val = m[j];
            if (val > best || (val == best && j < bidx)) { best = val; bidx = j; }
        }
        bv[tid] = best; bi[tid] = bidx;
        __syncthreads();
        for (int s = 128; s; s >>= 1) {
            if (tid < s) {
                float v2 = bv[tid + s]; int i2 = bi[tid + s];
                if (v2 > bv[tid] || (v2 == bv[tid] && i2 < bi[tid])) { bv[tid] = v2; bi[tid] = i2; }
            }
            __syncthreads();
        }
        if (tid == 0) {
            g_top[b][h][t] = bi[0];
            m[bi[0]] = -3.4e38f;
        }
        __syncthreads();
    }
}

// ---------------- kernel 5: mean of v over keys ----------------
__global__ void k_meanv(const float* __restrict__ v) {
    int b = blockIdx.x;
    int tid = threadIdx.x;           // 256 threads
    int d = tid & 63, g = tid >> 6;  // 4 partial groups per d
    __shared__ float part[256];
    float s = 0.f;
    for (int kk = g; kk < L; kk += 4)
        s += v[((size_t)b * L + kk) * D + d];
    part[tid] = s;
    __syncthreads();
    if (tid < 64)
        g_meanv[b][tid] = (part[tid] + part[tid + 64] + part[tid + 128] + part[tid + 192]) * (1.0f / 1024.0f);
}

// ---------------- kernel 6: fill attn_out with broadcast mean(v) ----------------
__global__ void k_fill() {
    int idx = blockIdx.x * blockDim.x + threadIdx.x;
    if (idx >= BATCH * L * DMODEL) return;
    int b = idx >> 20;        // / (1024*1024)
    int d = idx & 63;         // feature within head
    ((float*)g_attn)[idx] = g_meanv[b][d];
}

// ---------------- kernel 7: attention rows for selected queries ----------------
__global__ void k_attention(const float* __restrict__ v) {
    int i = blockIdx.x, h = blockIdx.y, b = blockIdx.z;
    int qs = g_top[b][h][i];
    __shared__ float p[L];
    __shared__ float red[256];
    int tid = threadIdx.x;

    float mx = -3.4e38f;
    for (int j = tid; j < L; j += 256) {
        float s = g_S[b][qs][j] * 0.03125f;   // / sqrt(1024)
        p[j] = s;
        mx = fmaxf(mx, s);
    }
    red[tid] = mx;
    __syncthreads();
    for (int s = 128; s; s >>= 1) { if (tid < s) red[tid] = fmaxf(red[tid], red[tid + s]); __syncthreads(); }
    mx = red[0];
    __syncthreads();

    float sum = 0.f;
    for (int j = tid; j < L; j += 256) {
        float e = expf(p[j] - mx);
        p[j] = e;
        sum += e;
    }
    red[tid] = sum;
    __syncthreads();
    for (int s = 128; s; s >>= 1) { if (tid < s) red[tid] += red[tid + s]; __syncthreads(); }
    float rs = 1.0f / red[0];
    __syncthreads();

    int d = tid & 63, g = tid >> 6;
    float acc = 0.f;
    for (int kk = g; kk < L; kk += 4)
        acc += p[kk] * v[((size_t)b * L + kk) * D + d];
    red[tid] = acc;
    __syncthreads();
    if (tid < 64) {
        float r = red[tid] + red[tid + 64] + red[tid + 128] + red[tid + 192];
        g_attn[b][qs][h * D + tid] = r * rs;
    }
}

// ---------------- kernel 8: out = attn_out @ W_proj + b_proj (2048x1024x1024 fp32) ----------------
__global__ void k_proj_gemm(const float* __restrict__ W, const float* __restrict__ bias,
                            float* __restrict__ out) {
    __shared__ float As[16][132];   // padded to dodge store conflicts
    __shared__ float Bs[16][128];
    const float* A = &g_attn[0][0][0];   // 2048 x 1024
    int bm = blockIdx.y * 128;
    int bn = blockIdx.x * 128;
    int tid = threadIdx.x;
    int tx = tid & 15, ty = tid >> 4;
    float acc[8][8] = {};
    for (int k0 = 0; k0 < 1024; k0 += 16) {
#pragma unroll
        for (int t = tid; t < 128 * 16; t += 256) {
            int r = t >> 4, c = t & 15;
            As[c][r] = A[(size_t)(bm + r) * 1024 + (k0 + c)];
        }
#pragma unroll
        for (int t = tid; t < 16 * 128; t += 256) {
            int r = t >> 7, c = t & 127;
            Bs[r][c] = W[(size_t)(k0 + r) * 1024 + (bn + c)];
        }
        __syncthreads();
#pragma unroll
        for (int kk = 0; kk < 16; kk++) {
            float ra[8], rb[8];
#pragma unroll
            for (int m = 0; m < 8; m++) ra[m] = As[kk][ty * 8 + m];
#pragma unroll
            for (int n = 0; n < 8; n++) rb[n] = Bs[kk][tx * 8 + n];
#pragma unroll
            for (int m = 0; m < 8; m++)
#pragma unroll
                for (int n = 0; n < 8; n++)
                    acc[m][n] += ra[m] * rb[n];
        }
        __syncthreads();
    }
#pragma unroll
    for (int m = 0; m < 8; m++) {
        int row = bm + ty * 8 + m;
#pragma unroll
        for (int n = 0; n < 8; n++) {
            int col = bn + tx * 8 + n;
            out[(size_t)row * 1024 + col] = acc[m][n] + bias[col];
        }
    }
}

// ---------------- launch ----------------
extern "C" void kernel_launch(void* const* d_in, const int* in_sizes, int n_in,
                              void* d_out, int out_size) {
    const float* q    = (const float*)d_in[0];
    const float* k    = (const float*)d_in[1];
    const float* v    = (const float*)d_in[2];
    const float* W    = (const float*)d_in[3];
    const float* bias = (const float*)d_in[4];
    float* out = (float*)d_out;

    k_zero_cnt<<<(H_HEADS * BATCH * L + 255) / 256, 256>>>();

    dim3 gIdx((BATCH * USAMP + 255) / 256, H_HEADS);
    k_idx_counts<<<gIdx, 256>>>();

    dim3 gS(16, 16, BATCH);
    k_scores<<<gS, 256>>>(q, k);

    dim3 gM(L / 8, H_HEADS, BATCH);
    k_measure<<<gM, 256>>>();

    dim3 gT(H_HEADS, BATCH);
    k_topk<<<gT, 256>>>();

    k_meanv<<<BATCH, 256>>>(v);

    k_fill<<<(BATCH * L * DMODEL) / 256, 256>>>();

    dim3 gA(USEL, H_HEADS, BATCH);
    k_attention<<<gA, 256>>>(v);

    dim3 gG(1024 / 128, 2048 / 128);
    k_proj_gemm<<<gG, 256>>>(W, bias, out);
}

// round 3
// speedup vs baseline: 1.2792x; 1.2792x over previous
#include <cuda_runtime.h>
#include <cuda_bf16.h>
#include <mma.h>
#include <cstdint>
#include <math.h>

using namespace nvcuda;

// Problem constants
#define H_HEADS 16
#define BATCH   2
#define L       1024
#define D       64
#define USAMP   7097
#define USEL    34
#define DMODEL  (H_HEADS * D)   // 1024
#define MROWS   (BATCH * L)     // 2048

// GEMM tiling
#define KC    32
#define TILE  (128 * KC)        // elements per smem operand tile
#define SMEM_DYN 65536          // max(2 stages * 4 tiles * 8KB, 128*128*4)

// ---------------- scratch (static device globals; no allocation) ----------------
__device__ float g_S[BATCH][L][L];            // q @ k^T per batch (8 MB)
__device__ int   g_cnt[H_HEADS][BATCH][L];    // sample histograms
__device__ float g_M[BATCH][H_HEADS][L];      // sparsity measure
__device__ int   g_top[BATCH][H_HEADS][USEL]; // selected query indices
__device__ float g_meanv[BATCH][D];           // mean over keys of v
// bf16 split of the attention-output matrix A (2048 x 1024): A = Ahi + Alo
__device__ __nv_bfloat16 g_Ahi[MROWS * DMODEL];
__device__ __nv_bfloat16 g_Alo[MROWS * DMODEL];
// bf16 split of W^T (stored [n][k]): W = Whi + Wlo
__device__ __nv_bfloat16 g_Whi[DMODEL * DMODEL];
__device__ __nv_bfloat16 g_Wlo[DMODEL * DMODEL];

// ---------------- threefry2x32 (JAX-compatible) ----------------
__device__ __forceinline__ uint32_t rotl32(uint32_t x, int d) {
    return (x << d) | (x >> (32 - d));
}

__device__ __forceinline__ void threefry2x32(uint32_t k0, uint32_t k1,
                                             uint32_t x0, uint32_t x1,
                                             uint32_t& o0, uint32_t& o1) {
    uint32_t ks2 = k0 ^ k1 ^ 0x1BD11BDAu;
    x0 += k0; x1 += k1;
#define TFR(r) { x0 += x1; x1 = rotl32(x1, (r)); x1 ^= x0; }
    TFR(13) TFR(15) TFR(26) TFR(6)   x0 += k1;  x1 += ks2 + 1u;
    TFR(17) TFR(29) TFR(16) TFR(24)  x0 += ks2; x1 += k0 + 2u;
    TFR(13) TFR(15) TFR(26) TFR(6)   x0 += k0;  x1 += k1 + 3u;
    TFR(17) TFR(29) TFR(16) TFR(24)  x0 += k1;  x1 += ks2 + 4u;
    TFR(13) TFR(15) TFR(26) TFR(6)   x0 += ks2; x1 += k0 + 5u;
#undef TFR
    o0 = x0; o1 = x1;
}

// ---------------- kernel 0: zero the histograms ----------------
__global__ void k_zero_cnt() {
    int i = blockIdx.x * blockDim.x + threadIdx.x;
    if (i < H_HEADS * BATCH * L) ((int*)g_cnt)[i] = 0;
}

// ---------------- kernel 1: sampled-index histograms via threefry ----------------
__global__ void k_idx_counts() {
    int i = blockIdx.x * blockDim.x + threadIdx.x;
    int h = blockIdx.y;
    if (i >= BATCH * USAMP) return;
    uint32_t hk0, hk1, s0, s1, b1, b2;
    threefry2x32(0u, 42u, 0u, (uint32_t)h, hk0, hk1);
    threefry2x32(hk0, hk1, 0u, 1u, s0, s1);
    threefry2x32(s0, s1, 0u, (uint32_t)i, b1, b2);
    uint32_t bits = b1 ^ b2;
    int j = (int)(bits & 1023u);
    int b = i / USAMP;
    atomicAdd(&g_cnt[h][b][j], 1);
}

// ---------------- kernel 2: S[b] = q[b] @ k[b]^T (fp32 exact; feeds top-k) ----------------
__global__ void k_scores(const float* __restrict__ q, const float* __restrict__ k) {
    __shared__ float qs[64][65];
    __shared__ float ks[64][65];
    int b  = blockIdx.z;
    int i0 = blockIdx.y * 64, j0 = blockIdx.x * 64;
    int tid = threadIdx.x;
    for (int t = tid; t < 4096; t += 256) {
        int r = t >> 6, c = t & 63;
        qs[r][c] = q[((size_t)b * L + i0 + r) * D + c];
        ks[r][c] = k[((size_t)b * L + j0 + r) * D + c];
    }
    __syncthreads();
    int tx = tid & 15, ty = tid >> 4;
    float acc[4][4] = {};
#pragma unroll 8
    for (int d = 0; d < 64; d++) {
        float a[4], bb[4];
#pragma unroll
        for (int r = 0; r < 4; r++) a[r] = qs[ty * 4 + r][d];
#pragma unroll
        for (int c = 0; c < 4; c++) bb[c] = ks[tx * 4 + c][d];
#pragma unroll
        for (int r = 0; r < 4; r++)
#pragma unroll
            for (int c = 0; c < 4; c++)
                acc[r][c] += a[r] * bb[c];
    }
#pragma unroll
    for (int r = 0; r < 4; r++)
#pragma unroll
        for (int c = 0; c < 4; c++)
            g_S[b][i0 + ty * 4 + r][j0 + tx * 4 + c] = acc[r][c];
}

// ---------------- kernel 3: M = masked max - count-weighted mean ----------------
__global__ void k_measure() {
    int b = blockIdx.z, h = blockIdx.y;
    int q0 = blockIdx.x * 8;
    __shared__ int cnt_s[L];
    int tid = threadIdx.x;
    for (int j = tid; j < L; j += 256) cnt_s[j] = g_cnt[h][b][j];
    __syncthreads();
    int w = tid >> 5, lane = tid & 31;
    int qr = q0 + w;
    const float* Srow = g_S[b][qr];
    float mx = -3.4e38f;
    float sum = 0.f;
    for (int j = lane; j < L; j += 32) {
        float s = Srow[j];
        int   c = cnt_s[j];
        if (c) mx = fmaxf(mx, s);
        sum += (float)c * s;
    }
#pragma unroll
    for (int off = 16; off; off >>= 1) {
        mx  = fmaxf(mx, __shfl_down_sync(0xffffffffu, mx, off));
        sum += __shfl_down_sync(0xffffffffu, sum, off);
    }
    if (lane == 0) g_M[b][h][qr] = mx - sum / 7097.0f;
}

// ---------------- kernel 4: iterative top-34 ----------------
__global__ void k_topk() {
    int h = blockIdx.x, b = blockIdx.y;
    __shared__ float m[L];
    __shared__ float bv[256];
    __shared__ int   bi[256];
    int tid = threadIdx.x;
    for (int j = tid; j < L; j += 256) m[j] = g_M[b][h][j];
    __syncthreads();
    for (int t = 0; t < USEL; t++) {
        float best = -3.4e38f; int bidx = L;
        for (int j = tid; j < L; j += 256) {
            float val = m[j];
            if (val > best || (val == best && j < bidx)) { best = val; bidx = j; }
        }
        bv[tid] = best; bi[tid] = bidx;
        __syncthreads();
        for (int s = 128; s; s >>= 1) {
            if (tid < s) {
                float v2 = bv[tid + s]; int i2 = bi[tid + s];
                if (v2 > bv[tid] || (v2 == bv[tid] && i2 < bi[tid])) { bv[tid] = v2; bi[tid] = i2; }
            }
            __syncthreads();
        }
        if (tid == 0) {
            g_top[b][h][t] = bi[0];
            m[bi[0]] = -3.4e38f;
        }
        __syncthreads();
    }
}

// ---------------- kernel 5: mean of v over keys ----------------
__global__ void k_meanv(const float* __restrict__ v) {
    int b = blockIdx.x;
    int tid = threadIdx.x;
    int d = tid & 63, g = tid >> 6;
    __shared__ float part[256];
    float s = 0.f;
    for (int kk = g; kk < L; kk += 4)
        s += v[((size_t)b * L + kk) * D + d];
    part[tid] = s;
    __syncthreads();
    if (tid < 64)
        g_meanv[b][tid] = (part[tid] + part[tid + 64] + part[tid + 128] + part[tid + 192]) * (1.0f / 1024.0f);
}

// ---------------- kernel 6: fill A (bf16 hi/lo) with broadcast mean(v) ----------------
__global__ void k_fill() {
    int idx = blockIdx.x * blockDim.x + threadIdx.x;
    if (idx >= MROWS * DMODEL) return;
    int b = idx >> 20;
    int d = idx & 63;
    float x = g_meanv[b][d];
    __nv_bfloat16 hi = __float2bfloat16(x);
    g_Ahi[idx] = hi;
    g_Alo[idx] = __float2bfloat16(x - __bfloat162float(hi));
}

// ---------------- kernel 7: attention rows for selected queries (writes bf16 split) ----------------
__global__ void k_attention(const float* __restrict__ v) {
    int i = blockIdx.x, h = blockIdx.y, b = blockIdx.z;
    int qs = g_top[b][h][i];
    __shared__ float p[L];
    __shared__ float red[256];
    int tid = threadIdx.x;

    float mx = -3.4e38f;
    for (int j = tid; j < L; j += 256) {
        float s = g_S[b][qs][j] * 0.03125f;
        p[j] = s;
        mx = fmaxf(mx, s);
    }
    red[tid] = mx;
    __syncthreads();
    for (int s = 128; s; s >>= 1) { if (tid < s) red[tid] = fmaxf(red[tid], red[tid + s]); __syncthreads(); }
    mx = red[0];
    __syncthreads();

    float sum = 0.f;
    for (int j = tid; j < L; j += 256) {
        float e = expf(p[j] - mx);
        p[j] = e;
        sum += e;
    }
    red[tid] = sum;
    __syncthreads();
    for (int s = 128; s; s >>= 1) { if (tid < s) red[tid] += red[tid + s]; __syncthreads(); }
    float rs = 1.0f / red[0];
    __syncthreads();

    int d = tid & 63, g = tid >> 6;
    float acc = 0.f;
    for (int kk = g; kk < L; kk += 4)
        acc += p[kk] * v[((size_t)b * L + kk) * D + d];
    red[tid] = acc;
    __syncthreads();
    if (tid < 64) {
        float r = (red[tid] + red[tid + 64] + red[tid + 128] + red[tid + 192]) * rs;
        size_t idx = (size_t)(b * L + qs) * DMODEL + h * D + tid;
        __nv_bfloat16 hi = __float2bfloat16(r);
        g_Ahi[idx] = hi;
        g_Alo[idx] = __float2bfloat16(r - __bfloat162float(hi));
    }
}

// ---------------- kernel 8a: split + transpose W into bf16 hi/lo [n][k] ----------------
__global__ void k_split_W(const float* __restrict__ W) {
    __shared__ float tile[32][33];
    int k0 = blockIdx.y * 32, n0 = blockIdx.x * 32;
    int tx = threadIdx.x, ty = threadIdx.y;   // 32 x 8
    for (int r = ty; r < 32; r += 8)
        tile[r][tx] = W[(size_t)(k0 + r) * DMODEL + n0 + tx];
    __syncthreads();
    for (int r = ty; r < 32; r += 8) {
        float x = tile[tx][r];   // = W[k0+tx][n0+r]
        __nv_bfloat16 hi = __float2bfloat16(x);
        size_t o = (size_t)(n0 + r) * DMODEL + k0 + tx;
        g_Whi[o] = hi;
        g_Wlo[o] = __float2bfloat16(x - __bfloat162float(hi));
    }
}

// ---------------- kernel 8b: wmma (HMMA) GEMM  out = A @ W + bias  (3x bf16 emulation) ----------------
__device__ __forceinline__ void load_stage(__nv_bfloat16* s, int bm, int bn, int k0, int tid) {
    for (int u = tid; u < 512; u += 256) {
        int row = u >> 2, c = (u & 3) * 8;
        size_t ga = (size_t)(bm + row) * DMODEL + k0 + c;
        size_t gb = (size_t)(bn + row) * DMODEL + k0 + c;
        int so = row * KC + c;
        *(uint4*)&s[so]            = *(const uint4*)&g_Ahi[ga];
        *(uint4*)&s[TILE + so]     = *(const uint4*)&g_Alo[ga];
        *(uint4*)&s[2 * TILE + so] = *(const uint4*)&g_Whi[gb];
        *(uint4*)&s[3 * TILE + so] = *(const uint4*)&g_Wlo[gb];
    }
}

__global__ void __launch_bounds__(256, 1) k_proj_wmma(const float* __restrict__ bias,
                                                      float* __restrict__ out) {
    extern __shared__ __nv_bfloat16 sm[];
    int tid = threadIdx.x;
    int w = tid >> 5;
    int wm = w & 1;       // 2 M-groups of 64 rows
    int wn = w >> 1;      // 4 N-groups of 32 cols
    int bm = blockIdx.y * 128, bn = blockIdx.x * 128;

    wmma::fragment<wmma::accumulator, 16, 16, 16, float> acc[4][2];
#pragma unroll
    for (int i = 0; i < 4; i++)
#pragma unroll
        for (int j = 0; j < 2; j++)
            wmma::fill_fragment(acc[i][j], 0.0f);

    load_stage(sm, bm, bn, 0, tid);
    __syncthreads();

    for (int c = 0; c < DMODEL / KC; c++) {
        int cur = c & 1;
        if (c + 1 < DMODEL / KC)
            load_stage(sm + (cur ^ 1) * 4 * TILE, bm, bn, (c + 1) * KC, tid);

        const __nv_bfloat16* s   = sm + cur * 4 * TILE;
        const __nv_bfloat16* Ahi = s;
        const __nv_bfloat16* Alo = s + TILE;
        const __nv_bfloat16* Bhi = s + 2 * TILE;
        const __nv_bfloat16* Blo = s + 3 * TILE;
#pragma unroll
        for (int kk = 0; kk < KC; kk += 16) {
            wmma::fragment<wmma::matrix_a, 16, 16, 16, __nv_bfloat16, wmma::row_major> ah[4], al[4];
            wmma::fragment<wmma::matrix_b, 16, 16, 16, __nv_bfloat16, wmma::col_major> bh[2], bl[2];
#pragma unroll
            for (int i = 0; i < 4; i++) {
                wmma::load_matrix_sync(ah[i], Ahi + (wm * 64 + i * 16) * KC + kk, KC);
                wmma::load_matrix_sync(al[i], Alo + (wm * 64 + i * 16) * KC + kk, KC);
            }
#pragma unroll
            for (int j = 0; j < 2; j++) {
                wmma::load_matrix_sync(bh[j], Bhi + (wn * 32 + j * 16) * KC + kk, KC);
                wmma::load_matrix_sync(bl[j], Blo + (wn * 32 + j * 16) * KC + kk, KC);
            }
#pragma unroll
            for (int i = 0; i < 4; i++)
#pragma unroll
                for (int j = 0; j < 2; j++) {
                    wmma::mma_sync(acc[i][j], ah[i], bh[j], acc[i][j]);
                    wmma::mma_sync(acc[i][j], ah[i], bl[j], acc[i][j]);
                    wmma::mma_sync(acc[i][j], al[i], bh[j], acc[i][j]);
                }
        }
        __syncthreads();
    }

    // epilogue: stage fp32 tile in smem, add bias, coalesced float4 stores
    float* fs = (float*)sm;
#pragma unroll
    for (int i = 0; i < 4; i++)
#pragma unroll
        for (int j = 0; j < 2; j++)
            wmma::store_matrix_sync(&fs[(wm * 64 + i * 16) * 128 + wn * 32 + j * 16],
                                    acc[i][j], 128, wmma::mem_row_major);
    __syncthreads();
    for (int u = tid; u < 128 * 128 / 4; u += 256) {
        int row = u >> 5, c4 = (u & 31) * 4;
        float4 vv = *(float4*)&fs[row * 128 + c4];
        float4 bb = *(const float4*)&bias[bn + c4];
        vv.x += bb.x; vv.y += bb.y; vv.z += bb.z; vv.w += bb.w;
        *(float4*)&out[(size_t)(bm + row) * DMODEL + bn + c4] = vv;
    }
}

// ---------------- launch ----------------
extern "C" void kernel_launch(void* const* d_in, const int* in_sizes, int n_in,
                              void* d_out, int out_size) {
    const float* q    = (const float*)d_in[0];
    const float* k    = (const float*)d_in[1];
    const float* v    = (const float*)d_in[2];
    const float* W    = (const float*)d_in[3];
    const float* bias = (const float*)d_in[4];
    float* out = (float*)d_out;

    cudaFuncSetAttribute(k_proj_wmma, cudaFuncAttributeMaxDynamicSharedMemorySize, SMEM_DYN);

    k_zero_cnt<<<(H_HEADS * BATCH * L + 255) / 256, 256>>>();

    dim3 gIdx((BATCH * USAMP + 255) / 256, H_HEADS);
    k_idx_counts<<<gIdx, 256>>>();

    dim3 gS(16, 16, BATCH);
    k_scores<<<gS, 256>>>(q, k);

    dim3 gM(L / 8, H_HEADS, BATCH);
    k_measure<<<gM, 256>>>();

    dim3 gT(H_HEADS, BATCH);
    k_topk<<<gT, 256>>>();

    k_meanv<<<BATCH, 256>>>(v);

    k_fill<<<(MROWS * DMODEL) / 256, 256>>>();

    dim3 gA(USEL, H_HEADS, BATCH);
    k_attention<<<gA, 256>>>(v);

    dim3 gW(DMODEL / 32, DMODEL / 32);
    k_split_W<<<gW, dim3(32, 8)>>>(W);

    dim3 gG(DMODEL / 128, MROWS / 128);
    k_proj_wmma<<<gG, 256, SMEM_DYN>>>(bias, out);
}

// round 4
// speedup vs baseline: 1.5231x; 1.1907x over previous
#include <cuda_runtime.h>
#include <cuda_bf16.h>
#include <mma.h>
#include <cstdint>
#include <math.h>

using namespace nvcuda;

// Problem constants
#define H_HEADS 16
#define BATCH   2
#define L       1024
#define D       64
#define USAMP   7097
#define USEL    34
#define DMODEL  (H_HEADS * D)   // 1024
#define MROWS   (BATCH * L)     // 2048

// GEMM tiling
#define KC    32
#define TILE  (128 * KC)
#define SMEM_DYN 65536

// PV tiling
#define NCH 16
#define CHK 64

// ---------------- scratch (static device globals; no allocation) ----------------
__device__ float g_S[BATCH][L][L];
__device__ int   g_cnt[H_HEADS][BATCH][L];
__device__ float g_M[BATCH][H_HEADS][L];
__device__ int   g_top[BATCH][H_HEADS][USEL];
__device__ float g_meanv[BATCH][D];
__device__ float g_P[BATCH][H_HEADS][USEL][L];          // unnormalized exp weights
__device__ float g_rs[BATCH][H_HEADS][USEL];            // reciprocal softmax sums
__device__ float g_pacc[BATCH][H_HEADS][USEL][NCH][64]; // per-chunk PV partials
__device__ __nv_bfloat16 g_Ahi[MROWS * DMODEL];
__device__ __nv_bfloat16 g_Alo[MROWS * DMODEL];
__device__ __nv_bfloat16 g_Whi[DMODEL * DMODEL];
__device__ __nv_bfloat16 g_Wlo[DMODEL * DMODEL];

// ---------------- threefry2x32 (JAX-compatible) ----------------
__device__ __forceinline__ uint32_t rotl32(uint32_t x, int d) {
    return (x << d) | (x >> (32 - d));
}

__device__ __forceinline__ void threefry2x32(uint32_t k0, uint32_t k1,
                                             uint32_t x0, uint32_t x1,
                                             uint32_t& o0, uint32_t& o1) {
    uint32_t ks2 = k0 ^ k1 ^ 0x1BD11BDAu;
    x0 += k0; x1 += k1;
#define TFR(r) { x0 += x1; x1 = rotl32(x1, (r)); x1 ^= x0; }
    TFR(13) TFR(15) TFR(26) TFR(6)   x0 += k1;  x1 += ks2 + 1u;
    TFR(17) TFR(29) TFR(16) TFR(24)  x0 += ks2; x1 += k0 + 2u;
    TFR(13) TFR(15) TFR(26) TFR(6)   x0 += k0;  x1 += k1 + 3u;
    TFR(17) TFR(29) TFR(16) TFR(24)  x0 += k1;  x1 += ks2 + 4u;
    TFR(13) TFR(15) TFR(26) TFR(6)   x0 += ks2; x1 += k0 + 5u;
#undef TFR
    o0 = x0; o1 = x1;
}

// ---------------- kernel 0: zero the histograms ----------------
__global__ void k_zero_cnt() {
    int i = blockIdx.x * blockDim.x + threadIdx.x;
    if (i < H_HEADS * BATCH * L) ((int*)g_cnt)[i] = 0;
}

// ---------------- kernel 1: sampled-index histograms via threefry ----------------
__global__ void k_idx_counts() {
    int i = blockIdx.x * blockDim.x + threadIdx.x;
    int h = blockIdx.y;
    if (i >= BATCH * USAMP) return;
    uint32_t hk0, hk1, s0, s1, b1, b2;
    threefry2x32(0u, 42u, 0u, (uint32_t)h, hk0, hk1);
    threefry2x32(hk0, hk1, 0u, 1u, s0, s1);
    threefry2x32(s0, s1, 0u, (uint32_t)i, b1, b2);
    uint32_t bits = b1 ^ b2;
    int j = (int)(bits & 1023u);
    int b = i / USAMP;
    atomicAdd(&g_cnt[h][b][j], 1);
}

// ---------------- kernel 2: S[b] = q[b] @ k[b]^T (fp32 exact; feeds top-k) ----------------
__global__ void k_scores(const float* __restrict__ q, const float* __restrict__ k) {
    __shared__ float qs[64][65];
    __shared__ float ks[64][65];
    int b  = blockIdx.z;
    int i0 = blockIdx.y * 64, j0 = blockIdx.x * 64;
    int tid = threadIdx.x;
    for (int t = tid; t < 4096; t += 256) {
        int r = t >> 6, c = t & 63;
        qs[r][c] = q[((size_t)b * L + i0 + r) * D + c];
        ks[r][c] = k[((size_t)b * L + j0 + r) * D + c];
    }
    __syncthreads();
    int tx = tid & 15, ty = tid >> 4;
    float acc[4][4] = {};
#pragma unroll 8
    for (int d = 0; d < 64; d++) {
        float a[4], bb[4];
#pragma unroll
        for (int r = 0; r < 4; r++) a[r] = qs[ty * 4 + r][d];
#pragma unroll
        for (int c = 0; c < 4; c++) bb[c] = ks[tx * 4 + c][d];
#pragma unroll
        for (int r = 0; r < 4; r++)
#pragma unroll
            for (int c = 0; c < 4; c++)
                acc[r][c] += a[r] * bb[c];
    }
#pragma unroll
    for (int r = 0; r < 4; r++)
#pragma unroll
        for (int c = 0; c < 4; c++)
            g_S[b][i0 + ty * 4 + r][j0 + tx * 4 + c] = acc[r][c];
}

// ---------------- kernel 3: M = masked max - count-weighted mean ----------------
__global__ void k_measure() {
    int b = blockIdx.z, h = blockIdx.y;
    int q0 = blockIdx.x * 8;
    __shared__ int cnt_s[L];
    int tid = threadIdx.x;
    for (int j = tid; j < L; j += 256) cnt_s[j] = g_cnt[h][b][j];
    __syncthreads();
    int w = tid >> 5, lane = tid & 31;
    int qr = q0 + w;
    const float* Srow = g_S[b][qr];
    float mx = -3.4e38f;
    float sum = 0.f;
    for (int j = lane; j < L; j += 32) {
        float s = Srow[j];
        int   c = cnt_s[j];
        if (c) mx = fmaxf(mx, s);
        sum += (float)c * s;
    }
#pragma unroll
    for (int off = 16; off; off >>= 1) {
        mx  = fmaxf(mx, __shfl_down_sync(0xffffffffu, mx, off));
        sum += __shfl_down_sync(0xffffffffu, sum, off);
    }
    if (lane == 0) g_M[b][h][qr] = mx - sum / 7097.0f;
}

// ---------------- kernel 4: top-34 via packed-u64 shfl reduce (1024 threads) ----------------
__global__ void k_topk() {
    int h = blockIdx.x, b = blockIdx.y;
    int tid = threadIdx.x;
    int wid = tid >> 5, lane = tid & 31;
    __shared__ unsigned long long sk[32];

    float val = g_M[b][h][tid];
    uint32_t ub = __float_as_uint(val);
    uint32_t u = (ub & 0x80000000u) ? ~ub : (ub | 0x80000000u);  // order-preserving
    unsigned long long key = ((unsigned long long)u << 10) | (unsigned long long)(1023 - tid);

    for (int t = 0; t < USEL; t++) {
        unsigned long long k2 = key;
#pragma unroll
        for (int off = 16; off; off >>= 1) {
            unsigned long long o = __shfl_down_sync(0xffffffffu, k2, off);
            if (o > k2) k2 = o;
        }
        if (lane == 0) sk[wid] = k2;
        __syncthreads();
        if (wid == 0) {
            unsigned long long k3 = sk[lane];
#pragma unroll
            for (int off = 16; off; off >>= 1) {
                unsigned long long o = __shfl_down_sync(0xffffffffu, k3, off);
                if (o > k3) k3 = o;
            }
            if (lane == 0) {
                sk[0] = k3;
                g_top[b][h][t] = 1023 - (int)(k3 & 1023ull);
            }
        }
        __syncthreads();
        int widx = 1023 - (int)(sk[0] & 1023ull);
        if (tid == widx) key = 0ull;
        __syncthreads();
    }
}

// ---------------- kernel 5: mean of v over keys ----------------
__global__ void k_meanv(const float* __restrict__ v) {
    int b = blockIdx.x;
    int tid = threadIdx.x;
    int d = tid & 63, g = tid >> 6;
    __shared__ float part[256];
    float s = 0.f;
    for (int kk = g; kk < L; kk += 4)
        s += v[((size_t)b * L + kk) * D + d];
    part[tid] = s;
    __syncthreads();
    if (tid < 64)
        g_meanv[b][tid] = (part[tid] + part[tid + 64] + part[tid + 128] + part[tid + 192]) * (1.0f / 1024.0f);
}

// ---------------- kernel 6: fill A (bf16 hi/lo) with broadcast mean(v) ----------------
__global__ void k_fill() {
    int idx = blockIdx.x * blockDim.x + threadIdx.x;
    if (idx >= MROWS * DMODEL) return;
    int b = idx >> 20;
    int d = idx & 63;
    float x = g_meanv[b][d];
    __nv_bfloat16 hi = __float2bfloat16(x);
    g_Ahi[idx] = hi;
    g_Alo[idx] = __float2bfloat16(x - __bfloat162float(hi));
}

// ---------------- kernel 7a: softmax weights for selected rows ----------------
__global__ void k_softmax() {
    int i = blockIdx.x, h = blockIdx.y, b = blockIdx.z;
    int qs = g_top[b][h][i];
    __shared__ float red[256];
    int tid = threadIdx.x;
    const float* Srow = g_S[b][qs];

    float mx = -3.4e38f;
    for (int j = tid; j < L; j += 256) mx = fmaxf(mx, Srow[j]);
    red[tid] = mx;
    __syncthreads();
    for (int s = 128; s; s >>= 1) { if (tid < s) red[tid] = fmaxf(red[tid], red[tid + s]); __syncthreads(); }
    float mxs = red[0] * 0.03125f;
    __syncthreads();

    float sum = 0.f;
    float* Prow = g_P[b][h][i];
    for (int j = tid; j < L; j += 256) {
        float e = __expf(Srow[j] * 0.03125f - mxs);
        Prow[j] = e;
        sum += e;
    }
    red[tid] = sum;
    __syncthreads();
    for (int s = 128; s; s >>= 1) { if (tid < s) red[tid] += red[tid + s]; __syncthreads(); }
    if (tid == 0) g_rs[b][h][i] = 1.0f / red[0];
}

// ---------------- kernel 7b: PV partials, v slice cached in smem ----------------
__global__ void k_pv(const float* __restrict__ v) {
    __shared__ float vs[CHK][64];     // 16 KB
    __shared__ float ps[USEL][CHK];   // 8.5 KB
    int ch = blockIdx.x, h = blockIdx.y, b = blockIdx.z;
    int k0 = ch * CHK;
    int tid = threadIdx.x;

    for (int u = tid; u < CHK * 64 / 4; u += 256) {
        int kk = u >> 4, c4 = (u & 15) * 4;
        *(float4*)&vs[kk][c4] = *(const float4*)&v[((size_t)b * L + k0 + kk) * D + c4];
    }
    for (int u = tid; u < USEL * CHK / 4; u += 256) {
        int row = u / (CHK / 4), c4 = (u % (CHK / 4)) * 4;
        *(float4*)&ps[row][c4] = *(const float4*)&g_P[b][h][row][k0 + c4];
    }
    __syncthreads();

    int r = tid >> 6, d = tid & 63;
    float acc[9];
#pragma unroll
    for (int i = 0; i < 9; i++) acc[i] = 0.f;

    for (int kk = 0; kk < CHK; kk += 4) {
        float v0 = vs[kk][d], v1 = vs[kk + 1][d], v2 = vs[kk + 2][d], v3 = vs[kk + 3][d];
#pragma unroll
        for (int i = 0; i < 9; i++) {
            int row = r + i * 4;
            if (row < USEL) {
                float4 p4 = *(float4*)&ps[row][kk];
                acc[i] += p4.x * v0 + p4.y * v1 + p4.z * v2 + p4.w * v3;
            }
        }
    }
#pragma unroll
    for (int i = 0; i < 9; i++) {
        int row = r + i * 4;
        if (row < USEL)
            g_pacc[b][h][row][ch][d] = acc[i];
    }
}

// ---------------- kernel 7c: sum partials, normalize, write bf16 split rows ----------------
__global__ void k_write() {
    int bh = blockIdx.x;
    int b = bh >> 4, h = bh & 15;
    int tid = threadIdx.x;
    int r = tid >> 6, d = tid & 63;
    for (int row = r; row < USEL; row += 4) {
        float s = 0.f;
#pragma unroll
        for (int c = 0; c < NCH; c++) s += g_pacc[b][h][row][c][d];
        float val = s * g_rs[b][h][row];
        int qs = g_top[b][h][row];
        size_t idx = (size_t)(b * L + qs) * DMODEL + h * D + d;
        __nv_bfloat16 hi = __float2bfloat16(val);
        g_Ahi[idx] = hi;
        g_Alo[idx] = __float2bfloat16(val - __bfloat162float(hi));
    }
}

// ---------------- kernel 8a: split + transpose W into bf16 hi/lo [n][k] ----------------
__global__ void k_split_W(const float* __restrict__ W) {
    __shared__ float tile[32][33];
    int k0 = blockIdx.y * 32, n0 = blockIdx.x * 32;
    int tx = threadIdx.x, ty = threadIdx.y;
    for (int r = ty; r < 32; r += 8)
        tile[r][tx] = W[(size_t)(k0 + r) * DMODEL + n0 + tx];
    __syncthreads();
    for (int r = ty; r < 32; r += 8) {
        float x = tile[tx][r];
        __nv_bfloat16 hi = __float2bfloat16(x);
        size_t o = (size_t)(n0 + r) * DMODEL + k0 + tx;
        g_Whi[o] = hi;
        g_Wlo[o] = __float2bfloat16(x - __bfloat162float(hi));
    }
}

// ---------------- kernel 8b: wmma (HMMA) GEMM out = A @ W + bias (3x bf16 emulation) ----------------
__device__ __forceinline__ void load_stage(__nv_bfloat16* s, int bm, int bn, int k0, int tid) {
    for (int u = tid; u < 512; u += 256) {
        int row = u >> 2, c = (u & 3) * 8;
        size_t ga = (size_t)(bm + row) * DMODEL + k0 + c;
        size_t gb = (size_t)(bn + row) * DMODEL + k0 + c;
        int so = row * KC + c;
        *(uint4*)&s[so]            = *(const uint4*)&g_Ahi[ga];
        *(uint4*)&s[TILE + so]     = *(const uint4*)&g_Alo[ga];
        *(uint4*)&s[2 * TILE + so] = *(const uint4*)&g_Whi[gb];
        *(uint4*)&s[3 * TILE + so] = *(const uint4*)&g_Wlo[gb];
    }
}

__global__ void __launch_bounds__(256, 1) k_proj_wmma(const float* __restrict__ bias,
                                                      float* __restrict__ out) {
    extern __shared__ __nv_bfloat16 sm[];
    int tid = threadIdx.x;
    int w = tid >> 5;
    int wm = w & 1;
    int wn = w >> 1;
    int bm = blockIdx.y * 128, bn = blockIdx.x * 128;

    wmma::fragment<wmma::accumulator, 16, 16, 16, float> acc[4][2];
#pragma unroll
    for (int i = 0; i < 4; i++)
#pragma unroll
        for (int j = 0; j < 2; j++)
            wmma::fill_fragment(acc[i][j], 0.0f);

    load_stage(sm, bm, bn, 0, tid);
    __syncthreads();

    for (int c = 0; c < DMODEL / KC; c++) {
        int cur = c & 1;
        if (c + 1 < DMODEL / KC)
            load_stage(sm + (cur ^ 1) * 4 * TILE, bm, bn, (c + 1) * KC, tid);

        const __nv_bfloat16* s   = sm + cur * 4 * TILE;
        const __nv_bfloat16* Ahi = s;
        const __nv_bfloat16* Alo = s + TILE;
        const __nv_bfloat16* Bhi = s + 2 * TILE;
        const __nv_bfloat16* Blo = s + 3 * TILE;
#pragma unroll
        for (int kk = 0; kk < KC; kk += 16) {
            wmma::fragment<wmma::matrix_a, 16, 16, 16, __nv_bfloat16, wmma::row_major> ah[4], al[4];
            wmma::fragment<wmma::matrix_b, 16, 16, 16, __nv_bfloat16, wmma::col_major> bh[2], bl[2];
#pragma unroll
            for (int i = 0; i < 4; i++) {
                wmma::load_matrix_sync(ah[i], Ahi + (wm * 64 + i * 16) * KC + kk, KC);
                wmma::load_matrix_sync(al[i], Alo + (wm * 64 + i * 16) * KC + kk, KC);
            }
#pragma unroll
            for (int j = 0; j < 2; j++) {
                wmma::load_matrix_sync(bh[j], Bhi + (wn * 32 + j * 16) * KC + kk, KC);
                wmma::load_matrix_sync(bl[j], Blo + (wn * 32 + j * 16) * KC + kk, KC);
            }
#pragma unroll
            for (int i = 0; i < 4; i++)
#pragma unroll
                for (int j = 0; j < 2; j++) {
                    wmma::mma_sync(acc[i][j], ah[i], bh[j], acc[i][j]);
                    wmma::mma_sync(acc[i][j], ah[i], bl[j], acc[i][j]);
                    wmma::mma_sync(acc[i][j], al[i], bh[j], acc[i][j]);
                }
        }
        __syncthreads();
    }

    float* fs = (float*)sm;
#pragma unroll
    for (int i = 0; i < 4; i++)
#pragma unroll
        for (int j = 0; j < 2; j++)
            wmma::store_matrix_sync(&fs[(wm * 64 + i * 16) * 128 + wn * 32 + j * 16],
                                    acc[i][j], 128, wmma::mem_row_major);
    __syncthreads();
    for (int u = tid; u < 128 * 128 / 4; u += 256) {
        int row = u >> 5, c4 = (u & 31) * 4;
        float4 vv = *(float4*)&fs[row * 128 + c4];
        float4 bb = *(const float4*)&bias[bn + c4];
        vv.x += bb.x; vv.y += bb.y; vv.z += bb.z; vv.w += bb.w;
        *(float4*)&out[(size_t)(bm + row) * DMODEL + bn + c4] = vv;
    }
}

// ---------------- launch ----------------
extern "C" void kernel_launch(void* const* d_in, const int* in_sizes, int n_in,
                              void* d_out, int out_size) {
    const float* q    = (const float*)d_in[0];
    const float* k    = (const float*)d_in[1];
    const float* v    = (const float*)d_in[2];
    const float* W    = (const float*)d_in[3];
    const float* bias = (const float*)d_in[4];
    float* out = (float*)d_out;

    cudaFuncSetAttribute(k_proj_wmma, cudaFuncAttributeMaxDynamicSharedMemorySize, SMEM_DYN);

    k_zero_cnt<<<(H_HEADS * BATCH * L + 255) / 256, 256>>>();

    dim3 gIdx((BATCH * USAMP + 255) / 256, H_HEADS);
    k_idx_counts<<<gIdx, 256>>>();

    dim3 gS(16, 16, BATCH);
    k_scores<<<gS, 256>>>(q, k);

    dim3 gM(L / 8, H_HEADS, BATCH);
    k_measure<<<gM, 256>>>();

    dim3 gT(H_HEADS, BATCH);
    k_topk<<<gT, 1024>>>();

    k_meanv<<<BATCH, 256>>>(v);

    k_fill<<<(MROWS * DMODEL) / 256, 256>>>();

    dim3 gSm(USEL, H_HEADS, BATCH);
    k_softmax<<<gSm, 256>>>();

    dim3 gPV(NCH, H_HEADS, BATCH);
    k_pv<<<gPV, 256>>>(v);

    k_write<<<BATCH * H_HEADS, 256>>>();

    dim3 gW(DMODEL / 32, DMODEL / 32);
    k_split_W<<<gW, dim3(32, 8)>>>(W);

    dim3 gG(DMODEL / 128, MROWS / 128);
    k_proj_wmma<<<gG, 256, SMEM_DYN>>>(bias, out);
}